// round 7
// baseline (speedup 1.0000x reference)
#include <cuda_runtime.h>

#define T 4096
#define B 2048
#define NS 7
#define PRED 64

__constant__ float c_lrs[NS] = {0.01f, 0.08f, 0.1f, 0.15f, 0.2f, 0.25f, 1.0f};

__device__ float g_errs[B * NS];
__device__ float g_finals[B * NS];
__device__ int   g_src[B];
__device__ int   g_sloc[B];

// ---------------- packed f32x2 helpers (sm_100+) ----------------
typedef unsigned long long u64;
__device__ __forceinline__ u64 pk(float x, float y) {
    u64 r; asm("mov.b64 %0, {%1, %2};" : "=l"(r) : "f"(x), "f"(y)); return r;
}
__device__ __forceinline__ void upk(u64 v, float& x, float& y) {
    asm("mov.b64 {%0, %1}, %2;" : "=f"(x), "=f"(y) : "l"(v));
}
__device__ __forceinline__ u64 f2fma(u64 a, u64 b, u64 c) {
    u64 d; asm("fma.rn.f32x2 %0, %1, %2, %3;" : "=l"(d) : "l"(a), "l"(b), "l"(c)); return d;
}
__device__ __forceinline__ u64 f2add(u64 a, u64 b) {
    u64 d; asm("add.rn.f32x2 %0, %1, %2;" : "=l"(d) : "l"(a), "l"(b)); return d;
}

// padded index for fused kernel's 16-wide segments (stride 17, odd)
#define SIDX2(i) ((i) + ((i) >> 4))
#define SROW2_SZ (T + (T >> 4))

// ---------------------------------------------------------------------------
// K1: per-row, 7 sigmas (one warp each). Clip is a provable no-op (level is a
// convex combination of row values -> |y-level| <= delta), so the recurrence
// is affine. Lane l handles TWO 64-step half-segments (2l, 2l+1) packed in
// f32x2 registers; warp scan composes the 64 segment transforms.
// smem layout: float2 slot (l*66 + j) = (elem 128l+j, elem 128l+64+j);
// lane stride 528B -> conflict-free LDS.128 (2 slots per load).
// ---------------------------------------------------------------------------
__global__ __launch_bounds__(256) void scan_kernel(const float* __restrict__ data) {
    __shared__ __align__(16) float s_pair[32 * 66 * 2];   // 16.9 KB
    int b = blockIdx.x;
    const float4* row4 = (const float4*)(data + (size_t)b * T);
    for (int i = threadIdx.x; i < T / 4; i += 256) {
        float4 v = __ldg(row4 + i);
        int t = i * 4;
        int l = t >> 7, w = t & 127, hi = w >> 6, j = w & 63;
        float* base = &s_pair[((l * 66 + j) << 1) + hi];   // 4 elems same (l,hi)
        base[0] = v.x; base[2] = v.y; base[4] = v.z; base[6] = v.w;
    }
    __syncthreads();

    int wq = threadIdx.x >> 5, lane = threadIdx.x & 31;
    if (wq >= NS) return;
    float sigma = c_lrs[wq];
    float a = 1.0f - sigma;
    u64 nsg = pk(-sigma, -sigma);
    const float4* seg = (const float4*)(s_pair + lane * 132);

    // pass 1: packed -c for (lo,hi) half-segments; c' = c + s*(y-c)
    u64 ncv = pk(0.0f, 0.0f);
#pragma unroll 8
    for (int k = 0; k < 32; k++) {
        float4 v = seg[k];
        u64 y0 = pk(v.x, v.y);
        u64 y1 = pk(v.z, v.w);
        u64 u0 = f2add(y0, ncv); ncv = f2fma(nsg, u0, ncv);
        u64 u1 = f2add(y1, ncv); ncv = f2fma(nsg, u1, ncv);
    }
    float c_lo, c_hi; { float x, y; upk(ncv, x, y); c_lo = -x; c_hi = -y; }

    float A64 = a;
#pragma unroll
    for (int i = 0; i < 6; i++) A64 *= A64;          // a^64
    float A128 = A64 * A64;
    float ccomb = fmaf(A64, c_lo, c_hi);             // hi o lo constant

    // warp inclusive scan composing (A128, ccomb), earlier lanes first
    float Ai = A128, ci = ccomb;
#pragma unroll
    for (int off = 1; off < 32; off <<= 1) {
        float Ap = __shfl_up_sync(0xffffffffu, Ai, off);
        float cp = __shfl_up_sync(0xffffffffu, ci, off);
        if (lane >= off) { ci = fmaf(Ai, cp, ci); Ai *= Ap; }
    }
    float Ae = __shfl_up_sync(0xffffffffu, Ai, 1);
    float ce = __shfl_up_sync(0xffffffffu, ci, 1);
    float y00 = s_pair[0];                           // element t=0
    float L_lo = (lane == 0) ? y00 : fmaf(Ae, y00, ce);
    float L_hi = fmaf(A64, L_lo, c_lo);
    float Lfin = fmaf(__shfl_sync(0xffffffffu, Ai, 31), y00,
                      __shfl_sync(0xffffffffu, ci, 31));

    // pass 2: exact packed recurrence from segment starts; L' = L + s*d
    u64 nL  = pk(-L_lo, -L_hi);
    u64 err = pk(0.0f, 0.0f);
#pragma unroll 8
    for (int k = 0; k < 32; k++) {
        float4 v = seg[k];
        u64 y0 = pk(v.x, v.y);
        u64 y1 = pk(v.z, v.w);
        u64 d0 = f2add(y0, nL);
        err = f2fma(d0, d0, err);
        nL  = f2fma(nsg, d0, nL);
        u64 d1 = f2add(y1, nL);
        err = f2fma(d1, d1, err);
        nL  = f2fma(nsg, d1, nL);
    }
    float elo, ehi; upk(err, elo, ehi);
    float e = elo + ehi;
#pragma unroll
    for (int off = 16; off; off >>= 1)
        e += __shfl_down_sync(0xffffffffu, e, off);
    if (lane == 0) {
        g_errs[b * NS + wq]   = e * (1.0f / (float)T);
        g_finals[b * NS + wq] = Lfin;
    }
}

// ---------------------------------------------------------------------------
// K2: batch-sequential pick via two-level warp scans (prefix-min of row
// minima -> improve flags; prefix-max of improving indices -> src row).
// ---------------------------------------------------------------------------
__global__ __launch_bounds__(1024) void pick_kernel() {
    __shared__ float s_e[B];
    __shared__ int   s_l[B];
    __shared__ float s_part[32];
    int tid = threadIdx.x, lane = tid & 31, wid = tid >> 5;

    float e0 = INFINITY, e1 = INFINITY; int l0 = 0, l1 = 0;
#pragma unroll
    for (int s = 0; s < NS; s++) {
        float a0 = g_errs[(2 * tid) * NS + s];
        float a1 = g_errs[(2 * tid + 1) * NS + s];
        if (a0 < e0) { e0 = a0; l0 = s; }            // strict < -> first argmin
        if (a1 < e1) { e1 = a1; l1 = s; }
    }
    s_e[2 * tid] = e0; s_l[2 * tid] = l0;
    s_e[2 * tid + 1] = e1; s_l[2 * tid + 1] = l1;

    // --- prefix-min over pairs ---
    float w = fminf(e0, e1);
#pragma unroll
    for (int off = 1; off < 32; off <<= 1) {
        float p = __shfl_up_sync(0xffffffffu, w, off);
        if (lane >= off) w = fminf(w, p);
    }
    if (lane == 31) s_part[wid] = w;
    __syncthreads();
    if (wid == 0) {
        float v = s_part[lane];
#pragma unroll
        for (int off = 1; off < 32; off <<= 1) {
            float p = __shfl_up_sync(0xffffffffu, v, off);
            if (lane >= off) v = fminf(v, p);
        }
        s_part[lane] = v;
    }
    __syncthreads();
    float wExcl = (wid == 0) ? INFINITY : s_part[wid - 1];
    float lExcl = __shfl_up_sync(0xffffffffu, w, 1);
    if (lane == 0) lExcl = INFINITY;
    float exclPair = fminf(wExcl, lExcl);            // prefix-min before b=2*tid
    int imp0 = e0 < exclPair;
    int imp1 = e1 < fminf(exclPair, e0);
    __syncthreads();                                  // s_part reuse guard

    // --- prefix-max of improving indices ---
    float c0 = imp0 ? (float)(2 * tid) : -1.0f;
    float c1 = imp1 ? (float)(2 * tid + 1) : -1.0f;
    float m = fmaxf(c0, c1);
#pragma unroll
    for (int off = 1; off < 32; off <<= 1) {
        float p = __shfl_up_sync(0xffffffffu, m, off);
        if (lane >= off) m = fmaxf(m, p);
    }
    if (lane == 31) s_part[wid] = m;
    __syncthreads();
    if (wid == 0) {
        float v = s_part[lane];
#pragma unroll
        for (int off = 1; off < 32; off <<= 1) {
            float p = __shfl_up_sync(0xffffffffu, v, off);
            if (lane >= off) v = fmaxf(v, p);
        }
        s_part[lane] = v;
    }
    __syncthreads();
    float wE = (wid == 0) ? -1.0f : s_part[wid - 1];
    float lE = __shfl_up_sync(0xffffffffu, m, 1);
    if (lane == 0) lE = -1.0f;
    float ex = fmaxf(wE, lE);
    int src0 = (int)fmaxf(ex, c0);                   // row 0 always improves
    int src1 = (int)fmaxf(fmaxf(ex, c0), c1);
    g_src[2 * tid] = src0;      g_sloc[2 * tid] = s_l[src0];
    g_src[2 * tid + 1] = src1;  g_sloc[2 * tid + 1] = s_l[src1];
}

// ---------------------------------------------------------------------------
// K3 (fused): block b recomputes filt of row src[b] via 256-thread affine
// block scan, then writes out1[b] = data[b] - filt straight from registers,
// plus the 64-wide flat forecast.
// ---------------------------------------------------------------------------
__global__ __launch_bounds__(256) void fused_out_kernel(
    const float* __restrict__ data, float* __restrict__ out1,
    float* __restrict__ out_pr) {
    __shared__ float s_row[SROW2_SZ];
    __shared__ float sA[256], sC[256];

    int b = blockIdx.x;
    int src  = g_src[b];
    int sloc = g_sloc[b];
    float sigma = c_lrs[sloc];
    float a = 1.0f - sigma;
    const float* srow = data + (size_t)src * T;
    int t = threadIdx.x;

    for (int i = t; i < T; i += 256)
        s_row[SIDX2(i)] = __ldg(srow + i);
    __syncthreads();

    const int SEG = T / 256;                          // 16
    int base = t * SEG;
    float A = a;
#pragma unroll
    for (int i = 0; i < 4; i++) A *= A;               // a^16

    float c = 0.0f;
#pragma unroll
    for (int j = 0; j < SEG; j++)
        c = fmaf(a, c, sigma * s_row[SIDX2(base + j)]);

    sA[t] = A; sC[t] = c;
    __syncthreads();
    float Ai = A, ci = c;
    for (int off = 1; off < 256; off <<= 1) {
        float Ap = 0.0f, cp = 0.0f;
        if (t >= off) { Ap = sA[t - off]; cp = sC[t - off]; }
        __syncthreads();
        if (t >= off) { ci = fmaf(Ai, cp, ci); Ai *= Ap; }
        sA[t] = Ai; sC[t] = ci;
        __syncthreads();
    }
    float y0 = s_row[0];
    float L = (t == 0) ? y0 : fmaf(sA[t - 1], y0, sC[t - 1]);

    // pass 2 fused with output: filt[j] = pre-update level L; out = data_b - L
    const float4* drow = (const float4*)(data + (size_t)b * T);
    float4* orow = (float4*)(out1 + (size_t)b * T);
#pragma unroll
    for (int q = 0; q < SEG / 4; q++) {
        float4 dv = __ldg(drow + t * (SEG / 4) + q);
        float4 r;
        {
            float y = s_row[SIDX2(base + q * 4 + 0)];
            r.x = dv.x - L; L = fmaf(sigma, y - L, L);
        }
        {
            float y = s_row[SIDX2(base + q * 4 + 1)];
            r.y = dv.y - L; L = fmaf(sigma, y - L, L);
        }
        {
            float y = s_row[SIDX2(base + q * 4 + 2)];
            r.z = dv.z - L; L = fmaf(sigma, y - L, L);
        }
        {
            float y = s_row[SIDX2(base + q * 4 + 3)];
            r.w = dv.w - L; L = fmaf(sigma, y - L, L);
        }
        orow[t * (SEG / 4) + q] = r;
    }

    if (t < PRED / 4) {
        float pv = g_finals[b * NS + sloc];
        ((float4*)(out_pr + (size_t)b * PRED))[t] = make_float4(pv, pv, pv, pv);
    }
}

// ---------------------------------------------------------------------------
extern "C" void kernel_launch(void* const* d_in, const int* in_sizes, int n_in,
                              void* d_out, int out_size) {
    const float* data = (const float*)d_in[0];
    float* out = (float*)d_out;
    float* out1 = out;                       // [B, T]  data - sm
    float* out_pr = out + (size_t)B * T;     // [B, 64] forecast

    scan_kernel<<<B, 256>>>(data);
    pick_kernel<<<1, 1024>>>();
    fused_out_kernel<<<B, 256>>>(data, out1, out_pr);
}

// round 8
// speedup vs baseline: 1.1005x; 1.1005x over previous
#include <cuda_runtime.h>

#define T 4096
#define B 2048
#define NS 7
#define PRED 64

__constant__ float c_lrs[NS] = {0.01f, 0.08f, 0.1f, 0.15f, 0.2f, 0.25f, 1.0f};
// log2(1 - sigma) for the 6 non-unit sigmas
__constant__ float c_l2a[6] = {
    -0.014499569695115089f, -0.12029423371771177f, -0.15200309344504997f,
    -0.23446525363702297f,  -0.32192809488736235f, -0.4150374992788438f};

__device__ float g_errs[B * NS];
__device__ float g_finals[B * NS];
__device__ int   g_src[B];
__device__ int   g_sloc[B];

// ---------------- packed f32x2 helpers (sm_100+) ----------------
typedef unsigned long long u64;
__device__ __forceinline__ u64 pk(float x, float y) {
    u64 r; asm("mov.b64 %0, {%1, %2};" : "=l"(r) : "f"(x), "f"(y)); return r;
}
__device__ __forceinline__ void upk(u64 v, float& x, float& y) {
    asm("mov.b64 {%0, %1}, %2;" : "=f"(x), "=f"(y) : "l"(v));
}
__device__ __forceinline__ u64 f2fma(u64 a, u64 b, u64 c) {
    u64 d; asm("fma.rn.f32x2 %0, %1, %2, %3;" : "=l"(d) : "l"(a), "l"(b), "l"(c)); return d;
}
__device__ __forceinline__ u64 f2add(u64 a, u64 b) {
    u64 d; asm("add.rn.f32x2 %0, %1, %2;" : "=l"(d) : "l"(a), "l"(b)); return d;
}

// staging pad: 4 words per 16 -> stride 20; float4-aligned for i%4==0,
// per-lane read stride 20 words -> conflict-free within 8-lane phases
#define SIDX20(i) ((i) + (((i) >> 4) << 2))

// padded index for fused kernel's 16-wide segments (stride 17, odd)
#define SIDX2(i) ((i) + ((i) >> 4))
#define SROW2_SZ (T + (T >> 4))

// ---------------------------------------------------------------------------
// K1: one block per row. Each thread owns 16 register-resident elements and
// computes ALL sigmas (clip is a provable no-op -> affine recurrence).
// smem data traffic: one 16KB write + one 16KB read per block (vs 14x that
// for warp-per-sigma). Sigma pairs packed in f32x2; sigma=1.0 special-cased.
// ---------------------------------------------------------------------------
__global__ __launch_bounds__(256) void scan_kernel(const float* __restrict__ data) {
    __shared__ __align__(16) float s_d[5120];     // 20 KB staged row (padded)
    __shared__ float s_cw[8 * 6];
    __shared__ float s_er[8 * 7];
    int b = blockIdx.x;
    int tid = threadIdx.x, lane = tid & 31, wid = tid >> 5;
    const float4* row4 = (const float4*)(data + (size_t)b * T);
#pragma unroll
    for (int k = 0; k < 4; k++) {
        int i4 = tid + k * 256;
        float4 v = __ldg(row4 + i4);
        *(float4*)(s_d + SIDX20(i4 * 4)) = v;
    }
    __syncthreads();

    float y[16];
#pragma unroll
    for (int q = 0; q < 4; q++) {
        float4 v = *(const float4*)(s_d + tid * 20 + q * 4);
        y[q * 4 + 0] = v.x; y[q * 4 + 1] = v.y;
        y[q * 4 + 2] = v.z; y[q * 4 + 3] = v.w;
    }
    float y0 = s_d[0];
    float prev = (tid == 0) ? y[0] : s_d[tid * 20 - 5];   // element 16*tid-1

    // ---- pass 1: segment constants for 6 packed sigmas ----
    u64 nsg[3], nc[3];
#pragma unroll
    for (int p = 0; p < 3; p++) {
        nsg[p] = pk(-c_lrs[2 * p], -c_lrs[2 * p + 1]);
        nc[p]  = pk(0.f, 0.f);
    }
#pragma unroll
    for (int j = 0; j < 16; j++) {
        u64 yy = pk(y[j], y[j]);
#pragma unroll
        for (int p = 0; p < 3; p++) {
            u64 u = f2add(yy, nc[p]);              // y - c
            nc[p] = f2fma(nsg[p], u, nc[p]);       // c += s*(y-c)  (negated)
        }
    }
    float cseg[6];
#pragma unroll
    for (int p = 0; p < 3; p++) {
        float x0, x1; upk(nc[p], x0, x1);
        cseg[2 * p] = -x0; cseg[2 * p + 1] = -x1;
    }

    // ---- per-sigma warp scan of c (multiplier = a^16 powers) ----
    float a512s[6], cles[6];
#pragma unroll
    for (int s = 0; s < 6; s++) {
        float a = 1.0f - c_lrs[s];
        float A16 = a * a; A16 *= A16; A16 *= A16; A16 *= A16;   // a^16
        float m = A16;
        float ci = cseg[s];
#pragma unroll
        for (int k = 0; k < 5; k++) {
            float cp = __shfl_up_sync(0xffffffffu, ci, 1u << k);
            if (lane >= (1 << k)) ci = fmaf(m, cp, ci);
            m *= m;
        }                                           // m = a^512
        float cle = __shfl_up_sync(0xffffffffu, ci, 1);
        if (lane == 0) cle = 0.f;
        if (lane == 31) s_cw[wid * 6 + s] = ci;
        a512s[s] = m; cles[s] = cle;
    }
    __syncthreads();

    // ---- cross-warp combine + per-thread start level ----
    float Ls[6];
#pragma unroll
    for (int s = 0; s < 6; s++) {
        float E = 0.f;
        for (int w = 0; w < wid; w++) E = fmaf(a512s[s], E, s_cw[w * 6 + s]);
        float P = exp2f((16.f * tid)  * c_l2a[s]);  // a^(16*tid)
        float Q = exp2f((16.f * lane) * c_l2a[s]);  // a^(16*lane)
        Ls[s] = fmaf(P, y0, fmaf(Q, E, cles[s]));
    }
    if (tid == 0) {
#pragma unroll
        for (int s = 0; s < 6; s++) {
            float a512 = a512s[s];
            float Ct = 0.f;
            for (int w = 0; w < 8; w++) Ct = fmaf(a512, Ct, s_cw[w * 6 + s]);
            float a4096 = a512 * a512; a4096 *= a4096; a4096 *= a4096;
            g_finals[b * NS + s] = fmaf(a4096, y0, Ct);
        }
    }
    if (tid == 255) g_finals[b * NS + 6] = y[15];   // sigma=1: final level = last y

    // ---- pass 2: exact recurrence from segment starts, err accumulate ----
    u64 nL[3], er[3];
#pragma unroll
    for (int p = 0; p < 3; p++) {
        nL[p] = pk(-Ls[2 * p], -Ls[2 * p + 1]);
        er[p] = pk(0.f, 0.f);
    }
    float L6 = prev, e6 = 0.f;                      // sigma=1 path
#pragma unroll
    for (int j = 0; j < 16; j++) {
        u64 yy = pk(y[j], y[j]);
#pragma unroll
        for (int p = 0; p < 3; p++) {
            u64 d = f2add(yy, nL[p]);
            er[p] = f2fma(d, d, er[p]);
            nL[p] = f2fma(nsg[p], d, nL[p]);
        }
        float d6 = y[j] - L6;
        e6 = fmaf(d6, d6, e6);
        L6 = y[j];
    }
    float e[7];
#pragma unroll
    for (int p = 0; p < 3; p++) upk(er[p], e[2 * p], e[2 * p + 1]);
    e[6] = e6;
#pragma unroll
    for (int s = 0; s < 7; s++) {
#pragma unroll
        for (int off = 16; off; off >>= 1)
            e[s] += __shfl_down_sync(0xffffffffu, e[s], off);
    }
    if (lane == 0) {
#pragma unroll
        for (int s = 0; s < 7; s++) s_er[wid * 7 + s] = e[s];
    }
    __syncthreads();
    if (tid < 7) {
        float acc = 0.f;
#pragma unroll
        for (int w = 0; w < 8; w++) acc += s_er[w * 7 + tid];
        g_errs[b * NS + tid] = acc * (1.0f / (float)T);
    }
}

// ---------------------------------------------------------------------------
// K2: batch-sequential pick as parallel prefix scans (R4-proven version).
// ---------------------------------------------------------------------------
__global__ void pick_kernel() {
    __shared__ float s_rmin[B];
    __shared__ int   s_loc[B];
    __shared__ float bufA[B];
    __shared__ float bufB[B];
    int tid = threadIdx.x;

#pragma unroll
    for (int k = 0; k < 2; k++) {
        int b = tid + k * 1024;
        float best = INFINITY; int bi = 0;
#pragma unroll
        for (int s = 0; s < NS; s++) {
            float e = g_errs[b * NS + s];
            if (e < best) { best = e; bi = s; }    // strict < -> first argmin
        }
        s_rmin[b] = best; s_loc[b] = bi; bufA[b] = best;
    }
    __syncthreads();

    float* in = bufA; float* out = bufB;
    for (int off = 1; off < B; off <<= 1) {
#pragma unroll
        for (int k = 0; k < 2; k++) {
            int b = tid + k * 1024;
            float v = in[b];
            if (b >= off) v = fminf(v, in[b - off]);
            out[b] = v;
        }
        __syncthreads();
        float* tmp = in; in = out; out = tmp;
    }
#pragma unroll
    for (int k = 0; k < 2; k++) {
        int b = tid + k * 1024;
        float epm = (b == 0) ? INFINITY : in[b - 1];
        int imp = (s_rmin[b] < epm) ? 1 : 0;
        out[b] = imp ? (float)b : -1.0f;
    }
    __syncthreads();

    float* in2 = out; float* out2 = in;
    for (int off = 1; off < B; off <<= 1) {
#pragma unroll
        for (int k = 0; k < 2; k++) {
            int b = tid + k * 1024;
            float v = in2[b];
            if (b >= off) v = fmaxf(v, in2[b - off]);
            out2[b] = v;
        }
        __syncthreads();
        float* tmp = in2; in2 = out2; out2 = tmp;
    }

#pragma unroll
    for (int k = 0; k < 2; k++) {
        int b = tid + k * 1024;
        int src = (int)in2[b];
        g_src[b]  = src;
        g_sloc[b] = s_loc[src];
    }
}

// ---------------------------------------------------------------------------
// K3 (fused, R4-proven version): block b recomputes filt of row src[b] via a
// 256-thread affine block scan, then writes out1[b] = data[b] - filt and the
// 64-wide flat forecast.
// ---------------------------------------------------------------------------
__global__ __launch_bounds__(256) void fused_out_kernel(
    const float* __restrict__ data, float* __restrict__ out1,
    float* __restrict__ out_pr) {
    __shared__ float s_row[SROW2_SZ];
    __shared__ float sA[256], sC[256];

    int b = blockIdx.x;
    int src  = g_src[b];
    int sloc = g_sloc[b];
    float sigma = c_lrs[sloc];
    float a = 1.0f - sigma;
    const float* srow = data + (size_t)src * T;
    int t = threadIdx.x;

    for (int i = t; i < T; i += 256)
        s_row[SIDX2(i)] = __ldg(srow + i);
    __syncthreads();

    const int SEG = T / 256;                          // 16
    int base = t * SEG;
    float A = a;
#pragma unroll
    for (int i = 0; i < 4; i++) A *= A;               // a^16

    float c = 0.0f;
#pragma unroll
    for (int j = 0; j < SEG; j++)
        c = fmaf(a, c, sigma * s_row[SIDX2(base + j)]);

    sA[t] = A; sC[t] = c;
    __syncthreads();
    float Ai = A, ci = c;
    for (int off = 1; off < 256; off <<= 1) {
        float Ap = 0.0f, cp = 0.0f;
        if (t >= off) { Ap = sA[t - off]; cp = sC[t - off]; }
        __syncthreads();
        if (t >= off) { ci = fmaf(Ai, cp, ci); Ai *= Ap; }
        sA[t] = Ai; sC[t] = ci;
        __syncthreads();
    }
    float y0 = s_row[0];
    float L = (t == 0) ? y0 : fmaf(sA[t - 1], y0, sC[t - 1]);

    // pass 2: overwrite src row in smem with its filt values
#pragma unroll
    for (int j = 0; j < SEG; j++) {
        int idx = SIDX2(base + j);
        float y = s_row[idx];
        s_row[idx] = L;                // filt[t] = pre-update level
        float d = y - L;
        L = fmaf(sigma, d, L);
    }
    __syncthreads();

    // out1[b] = data[b] - filt (float4 global, scalar smem reads)
    const float4* drow = (const float4*)(data + (size_t)b * T);
    float4* orow = (float4*)(out1 + (size_t)b * T);
    for (int i = t; i < T / 4; i += 256) {
        float4 dv = __ldg(drow + i);
        int j = i * 4;
        float4 r;
        r.x = dv.x - s_row[SIDX2(j)];
        r.y = dv.y - s_row[SIDX2(j + 1)];
        r.z = dv.z - s_row[SIDX2(j + 2)];
        r.w = dv.w - s_row[SIDX2(j + 3)];
        orow[i] = r;
    }

    if (t < PRED / 4) {
        float pv = g_finals[b * NS + sloc];
        ((float4*)(out_pr + (size_t)b * PRED))[t] = make_float4(pv, pv, pv, pv);
    }
}

// ---------------------------------------------------------------------------
extern "C" void kernel_launch(void* const* d_in, const int* in_sizes, int n_in,
                              void* d_out, int out_size) {
    const float* data = (const float*)d_in[0];
    float* out = (float*)d_out;
    float* out1 = out;                       // [B, T]  data - sm
    float* out_pr = out + (size_t)B * T;     // [B, 64] forecast

    scan_kernel<<<B, 256>>>(data);
    pick_kernel<<<1, 1024>>>();
    fused_out_kernel<<<B, 256>>>(data, out1, out_pr);
}

// round 9
// speedup vs baseline: 1.1473x; 1.0425x over previous
#include <cuda_runtime.h>

#define T 4096
#define B 2048
#define NS 7
#define PRED 64

__constant__ float c_lrs[NS] = {0.01f, 0.08f, 0.1f, 0.15f, 0.2f, 0.25f, 1.0f};
// log2(1 - sigma) for the 6 non-unit sigmas
__constant__ float c_l2a[6] = {
    -0.014499569695115089f, -0.12029423371771177f, -0.15200309344504997f,
    -0.23446525363702297f,  -0.32192809488736235f, -0.4150374992788438f};

__device__ float g_errs[B * NS];
__device__ float g_finals[B * NS];
__device__ int   g_src[B];
__device__ int   g_sloc[B];

// ---------------- packed f32x2 helpers (sm_100+) ----------------
typedef unsigned long long u64;
__device__ __forceinline__ u64 pk(float x, float y) {
    u64 r; asm("mov.b64 %0, {%1, %2};" : "=l"(r) : "f"(x), "f"(y)); return r;
}
__device__ __forceinline__ void upk(u64 v, float& x, float& y) {
    asm("mov.b64 {%0, %1}, %2;" : "=f"(x), "=f"(y) : "l"(v));
}
__device__ __forceinline__ u64 f2fma(u64 a, u64 b, u64 c) {
    u64 d; asm("fma.rn.f32x2 %0, %1, %2, %3;" : "=l"(d) : "l"(a), "l"(b), "l"(c)); return d;
}
__device__ __forceinline__ u64 f2add(u64 a, u64 b) {
    u64 d; asm("add.rn.f32x2 %0, %1, %2;" : "=l"(d) : "l"(a), "l"(b)); return d;
}
__device__ __forceinline__ u64 f2mul(u64 a, u64 b) {
    u64 d; asm("mul.rn.f32x2 %0, %1, %2;" : "=l"(d) : "l"(a), "l"(b)); return d;
}

// staging pad: 4 words per 16 -> stride 20; float4-aligned; per-lane read
// stride 20 words -> conflict-free within 8-lane phases
#define SIDX20(i) ((i) + (((i) >> 4) << 2))

// padded index for fused kernel's 16-wide segments (stride 17, odd)
#define SIDX2(i) ((i) + ((i) >> 4))
#define SROW2_SZ (T + (T >> 4))

// ---------------------------------------------------------------------------
// K1: one block per row, thread owns 16 contiguous elements, ALL sigma math
// packed in f32x2 pairs: p0=(.01,.08) p1=(.1,.15) p2=(.2,.25) p3=(1,1).
// Clip is a provable no-op -> affine recurrence; two passes + packed warp
// scan + cross-warp combine. y is staged in smem and re-read in pass 2 to
// keep register count low.
// ---------------------------------------------------------------------------
__global__ __launch_bounds__(256) void scan_kernel(const float* __restrict__ data) {
    __shared__ __align__(16) float s_d[5120];     // 20 KB padded row
    __shared__ u64 s_cw[8][3];
    __shared__ u64 s_er[8][4];
    int b = blockIdx.x;
    int tid = threadIdx.x, lane = tid & 31, wid = tid >> 5;
    const float4* row4 = (const float4*)(data + (size_t)b * T);
#pragma unroll
    for (int k = 0; k < 4; k++) {
        int i4 = tid + k * 256;
        *(float4*)(s_d + SIDX20(i4 * 4)) = __ldg(row4 + i4);
    }
    __syncthreads();

    const u64 SGN = 0x8000000080000000ULL;
    u64 nsg[4];
    nsg[0] = pk(-0.01f, -0.08f); nsg[1] = pk(-0.1f, -0.15f);
    nsg[2] = pk(-0.2f, -0.25f);  nsg[3] = pk(-1.0f, -1.0f);

    const float* yp = s_d + tid * 20;             // elems 16t+j at yp[j], j<16

    // ---- pass 1: negated segment constants for 3 packed pairs ----
    u64 nc[3] = {0, 0, 0};
#pragma unroll
    for (int q = 0; q < 4; q++) {
        float4 v = *(const float4*)(yp + q * 4);
        float e4[4] = {v.x, v.y, v.z, v.w};
#pragma unroll
        for (int j = 0; j < 4; j++) {
            u64 yy = pk(e4[j], e4[j]);
#pragma unroll
            for (int p = 0; p < 3; p++) {
                u64 u = f2add(yy, nc[p]);          // y - c
                nc[p] = f2fma(nsg[p], u, nc[p]);   // c += s*(y-c) (negated)
            }
        }
    }

    // ---- packed warp scan of segment constants (positive) ----
    u64 ci[3], mk[3];
    {
        u64 av[3] = {pk(0.99f, 0.92f), pk(0.9f, 0.85f), pk(0.8f, 0.75f)};
#pragma unroll
        for (int p = 0; p < 3; p++) {
            u64 x = av[p];
            x = f2mul(x, x); x = f2mul(x, x); x = f2mul(x, x); x = f2mul(x, x);
            mk[p] = x;                              // a^16
            ci[p] = nc[p] ^ SGN;                    // +c_seg
        }
    }
#pragma unroll
    for (int k = 0; k < 5; k++) {
#pragma unroll
        for (int p = 0; p < 3; p++) {
            u64 cp = __shfl_up_sync(0xffffffffu, ci[p], 1u << k);
            if (lane >= (1 << k)) ci[p] = f2fma(mk[p], cp, ci[p]);
            mk[p] = f2mul(mk[p], mk[p]);
        }
    }                                               // mk = a^512
    u64 cle[3];
#pragma unroll
    for (int p = 0; p < 3; p++) {
        cle[p] = __shfl_up_sync(0xffffffffu, ci[p], 1);
        if (lane == 0) cle[p] = 0;
    }
    if (lane == 31) {
        s_cw[wid][0] = ci[0]; s_cw[wid][1] = ci[1]; s_cw[wid][2] = ci[2];
    }
    __syncthreads();

    // ---- cross-warp combine + per-thread start levels ----
    float y0 = s_d[0];
    u64 y0p = pk(y0, y0);
    float t16 = 16.0f * tid, l16 = 16.0f * lane;
    u64 Ls[3];
#pragma unroll
    for (int p = 0; p < 3; p++) {
        u64 E = 0;
        for (int w = 0; w < wid; w++) E = f2fma(mk[p], E, s_cw[w][p]);
        u64 P = pk(exp2f(t16 * c_l2a[2 * p]), exp2f(t16 * c_l2a[2 * p + 1]));
        u64 Q = pk(exp2f(l16 * c_l2a[2 * p]), exp2f(l16 * c_l2a[2 * p + 1]));
        Ls[p] = f2fma(P, y0p, f2fma(Q, E, cle[p]));
    }
    if (tid == 0) {
#pragma unroll
        for (int p = 0; p < 3; p++) {
            u64 Ct = 0;
#pragma unroll
            for (int w = 0; w < 8; w++) Ct = f2fma(mk[p], Ct, s_cw[w][p]);
            u64 A = f2mul(mk[p], mk[p]); A = f2mul(A, A); A = f2mul(A, A);
            float flo, fhi; upk(f2fma(A, y0p, Ct), flo, fhi);
            g_finals[b * NS + 2 * p]     = flo;
            g_finals[b * NS + 2 * p + 1] = fhi;
        }
    }
    if (tid == 255) g_finals[b * NS + 6] = yp[15];  // sigma=1: last y

    // ---- pass 2: exact packed recurrence from segment starts ----
    float prev = (tid == 0) ? y0 : *(yp - 5);       // element 16t-1
    u64 nL[4], er[4];
#pragma unroll
    for (int p = 0; p < 3; p++) { nL[p] = Ls[p] ^ SGN; er[p] = 0; }
    nL[3] = pk(-prev, -prev); er[3] = 0;
#pragma unroll
    for (int q = 0; q < 4; q++) {
        float4 v = *(const float4*)(yp + q * 4);
        float e4[4] = {v.x, v.y, v.z, v.w};
#pragma unroll
        for (int j = 0; j < 4; j++) {
            u64 yy = pk(e4[j], e4[j]);
#pragma unroll
            for (int p = 0; p < 4; p++) {
                u64 d = f2add(yy, nL[p]);          // y - L
                er[p] = f2fma(d, d, er[p]);
                nL[p] = f2fma(nsg[p], d, nL[p]);   // L += s*d (negated)
            }
        }
    }
#pragma unroll
    for (int p = 0; p < 4; p++) {
#pragma unroll
        for (int off = 16; off; off >>= 1)
            er[p] = f2add(er[p], __shfl_down_sync(0xffffffffu, er[p], off));
    }
    if (lane == 0) {
        s_er[wid][0] = er[0]; s_er[wid][1] = er[1];
        s_er[wid][2] = er[2]; s_er[wid][3] = er[3];
    }
    __syncthreads();
    if (tid < 4) {
        u64 acc = 0;
#pragma unroll
        for (int w = 0; w < 8; w++) acc = f2add(acc, s_er[w][tid]);
        float lo, hi; upk(acc, lo, hi);
        if (tid < 3) {
            g_errs[b * NS + 2 * tid]     = lo * (1.0f / (float)T);
            g_errs[b * NS + 2 * tid + 1] = hi * (1.0f / (float)T);
        } else {
            g_errs[b * NS + 6] = lo * (1.0f / (float)T);
        }
    }
}

// ---------------------------------------------------------------------------
// K2: batch-sequential pick as parallel prefix scans (R4/R8-proven version).
// ---------------------------------------------------------------------------
__global__ void pick_kernel() {
    __shared__ float s_rmin[B];
    __shared__ int   s_loc[B];
    __shared__ float bufA[B];
    __shared__ float bufB[B];
    int tid = threadIdx.x;

#pragma unroll
    for (int k = 0; k < 2; k++) {
        int b = tid + k * 1024;
        float best = INFINITY; int bi = 0;
#pragma unroll
        for (int s = 0; s < NS; s++) {
            float e = g_errs[b * NS + s];
            if (e < best) { best = e; bi = s; }    // strict < -> first argmin
        }
        s_rmin[b] = best; s_loc[b] = bi; bufA[b] = best;
    }
    __syncthreads();

    float* in = bufA; float* out = bufB;
    for (int off = 1; off < B; off <<= 1) {
#pragma unroll
        for (int k = 0; k < 2; k++) {
            int b = tid + k * 1024;
            float v = in[b];
            if (b >= off) v = fminf(v, in[b - off]);
            out[b] = v;
        }
        __syncthreads();
        float* tmp = in; in = out; out = tmp;
    }
#pragma unroll
    for (int k = 0; k < 2; k++) {
        int b = tid + k * 1024;
        float epm = (b == 0) ? INFINITY : in[b - 1];
        int imp = (s_rmin[b] < epm) ? 1 : 0;
        out[b] = imp ? (float)b : -1.0f;
    }
    __syncthreads();

    float* in2 = out; float* out2 = in;
    for (int off = 1; off < B; off <<= 1) {
#pragma unroll
        for (int k = 0; k < 2; k++) {
            int b = tid + k * 1024;
            float v = in2[b];
            if (b >= off) v = fmaxf(v, in2[b - off]);
            out2[b] = v;
        }
        __syncthreads();
        float* tmp = in2; in2 = out2; out2 = tmp;
    }

#pragma unroll
    for (int k = 0; k < 2; k++) {
        int b = tid + k * 1024;
        int src = (int)in2[b];
        g_src[b]  = src;
        g_sloc[b] = s_loc[src];
    }
}

// ---------------------------------------------------------------------------
// K3 (fused, R4/R8-proven version): block b recomputes filt of row src[b]
// via a 256-thread affine block scan, then writes out1[b] = data[b] - filt
// and the 64-wide flat forecast.
// ---------------------------------------------------------------------------
__global__ __launch_bounds__(256) void fused_out_kernel(
    const float* __restrict__ data, float* __restrict__ out1,
    float* __restrict__ out_pr) {
    __shared__ float s_row[SROW2_SZ];
    __shared__ float sA[256], sC[256];

    int b = blockIdx.x;
    int src  = g_src[b];
    int sloc = g_sloc[b];
    float sigma = c_lrs[sloc];
    float a = 1.0f - sigma;
    const float* srow = data + (size_t)src * T;
    int t = threadIdx.x;

    for (int i = t; i < T; i += 256)
        s_row[SIDX2(i)] = __ldg(srow + i);
    __syncthreads();

    const int SEG = T / 256;                          // 16
    int base = t * SEG;
    float A = a;
#pragma unroll
    for (int i = 0; i < 4; i++) A *= A;               // a^16

    float c = 0.0f;
#pragma unroll
    for (int j = 0; j < SEG; j++)
        c = fmaf(a, c, sigma * s_row[SIDX2(base + j)]);

    sA[t] = A; sC[t] = c;
    __syncthreads();
    float Ai = A, ci = c;
    for (int off = 1; off < 256; off <<= 1) {
        float Ap = 0.0f, cp = 0.0f;
        if (t >= off) { Ap = sA[t - off]; cp = sC[t - off]; }
        __syncthreads();
        if (t >= off) { ci = fmaf(Ai, cp, ci); Ai *= Ap; }
        sA[t] = Ai; sC[t] = ci;
        __syncthreads();
    }
    float y0 = s_row[0];
    float L = (t == 0) ? y0 : fmaf(sA[t - 1], y0, sC[t - 1]);

    // pass 2: overwrite src row in smem with its filt values
#pragma unroll
    for (int j = 0; j < SEG; j++) {
        int idx = SIDX2(base + j);
        float y = s_row[idx];
        s_row[idx] = L;                // filt[t] = pre-update level
        float d = y - L;
        L = fmaf(sigma, d, L);
    }
    __syncthreads();

    // out1[b] = data[b] - filt (float4 global, scalar smem reads)
    const float4* drow = (const float4*)(data + (size_t)b * T);
    float4* orow = (float4*)(out1 + (size_t)b * T);
    for (int i = t; i < T / 4; i += 256) {
        float4 dv = __ldg(drow + i);
        int j = i * 4;
        float4 r;
        r.x = dv.x - s_row[SIDX2(j)];
        r.y = dv.y - s_row[SIDX2(j + 1)];
        r.z = dv.z - s_row[SIDX2(j + 2)];
        r.w = dv.w - s_row[SIDX2(j + 3)];
        orow[i] = r;
    }

    if (t < PRED / 4) {
        float pv = g_finals[b * NS + sloc];
        ((float4*)(out_pr + (size_t)b * PRED))[t] = make_float4(pv, pv, pv, pv);
    }
}

// ---------------------------------------------------------------------------
extern "C" void kernel_launch(void* const* d_in, const int* in_sizes, int n_in,
                              void* d_out, int out_size) {
    const float* data = (const float*)d_in[0];
    float* out = (float*)d_out;
    float* out1 = out;                       // [B, T]  data - sm
    float* out_pr = out + (size_t)B * T;     // [B, 64] forecast

    scan_kernel<<<B, 256>>>(data);
    pick_kernel<<<1, 1024>>>();
    fused_out_kernel<<<B, 256>>>(data, out1, out_pr);
}

// round 11
// speedup vs baseline: 1.1506x; 1.0028x over previous
#include <cuda_runtime.h>

#define T 4096
#define B 2048
#define NS 7
#define PRED 64

__constant__ float c_lrs[NS] = {0.01f, 0.08f, 0.1f, 0.15f, 0.2f, 0.25f, 1.0f};
// log2(1 - sigma) for the 6 non-unit sigmas
__constant__ float c_l2a[6] = {
    -0.014499569695115089f, -0.12029423371771177f, -0.15200309344504997f,
    -0.23446525363702297f,  -0.32192809488736235f, -0.4150374992788438f};

__device__ float g_errs[B * NS];
__device__ float g_finals[B * NS];
__device__ int   g_src[B];
__device__ int   g_sloc[B];

// ---------------- packed f32x2 helpers (sm_100+) ----------------
typedef unsigned long long u64;
__device__ __forceinline__ u64 pk(float x, float y) {
    u64 r; asm("mov.b64 %0, {%1, %2};" : "=l"(r) : "f"(x), "f"(y)); return r;
}
__device__ __forceinline__ void upk(u64 v, float& x, float& y) {
    asm("mov.b64 {%0, %1}, %2;" : "=f"(x), "=f"(y) : "l"(v));
}
__device__ __forceinline__ u64 f2fma(u64 a, u64 b, u64 c) {
    u64 d; asm("fma.rn.f32x2 %0, %1, %2, %3;" : "=l"(d) : "l"(a), "l"(b), "l"(c)); return d;
}
__device__ __forceinline__ u64 f2add(u64 a, u64 b) {
    u64 d; asm("add.rn.f32x2 %0, %1, %2;" : "=l"(d) : "l"(a), "l"(b)); return d;
}
__device__ __forceinline__ u64 f2mul(u64 a, u64 b) {
    u64 d; asm("mul.rn.f32x2 %0, %1, %2;" : "=l"(d) : "l"(a), "l"(b)); return d;
}

// staging pad: 4 words per 16 -> stride 20; float4-aligned; per-lane read
// stride 20 words -> conflict-free within 8-lane phases
#define SIDX20(i) ((i) + (((i) >> 4) << 2))

// padded index for fused kernel's 16-wide segments (stride 17, odd)
#define SIDX2(i) ((i) + ((i) >> 4))
#define SROW2_SZ (T + (T >> 4))

// ---------------------------------------------------------------------------
// K1: one block per row, thread owns 16 contiguous elements. Pairs packed in
// f32x2: p0=(.01,.08) p1=(.1,.15) p2=(.2,.25); sigma=1 is independent first
// differences (no recurrence). Clip is a provable no-op -> affine recurrence.
// ---------------------------------------------------------------------------
__global__ __launch_bounds__(256) void scan_kernel(const float* __restrict__ data) {
    __shared__ __align__(16) float s_d[5120];     // 20 KB padded row
    __shared__ u64 s_cw[8][3];
    __shared__ u64 s_er[8][4];
    int b = blockIdx.x;
    int tid = threadIdx.x, lane = tid & 31, wid = tid >> 5;
    const float4* row4 = (const float4*)(data + (size_t)b * T);
#pragma unroll
    for (int k = 0; k < 4; k++) {
        int i4 = tid + k * 256;
        *(float4*)(s_d + SIDX20(i4 * 4)) = __ldg(row4 + i4);
    }
    __syncthreads();

    const u64 SGN = 0x8000000080000000ULL;
    u64 nsg[3];
    nsg[0] = pk(-0.01f, -0.08f); nsg[1] = pk(-0.1f, -0.15f);
    nsg[2] = pk(-0.2f, -0.25f);

    const float* yp = s_d + tid * 20;             // elems 16t+j at yp[j], j<16

    // ---- pass 1: negated segment constants for 3 packed pairs ----
    u64 nc[3] = {0, 0, 0};
#pragma unroll
    for (int q = 0; q < 4; q++) {
        float4 v = *(const float4*)(yp + q * 4);
        float e4[4] = {v.x, v.y, v.z, v.w};
#pragma unroll
        for (int j = 0; j < 4; j++) {
            u64 yy = pk(e4[j], e4[j]);
#pragma unroll
            for (int p = 0; p < 3; p++) {
                u64 u = f2add(yy, nc[p]);          // y - c
                nc[p] = f2fma(nsg[p], u, nc[p]);   // c += s*(y-c) (negated)
            }
        }
    }

    // ---- packed warp scan of segment constants ----
    u64 ci[3], mk[3];
    {
        u64 av[3] = {pk(0.99f, 0.92f), pk(0.9f, 0.85f), pk(0.8f, 0.75f)};
#pragma unroll
        for (int p = 0; p < 3; p++) {
            u64 x = av[p];
            x = f2mul(x, x); x = f2mul(x, x); x = f2mul(x, x); x = f2mul(x, x);
            mk[p] = x;                              // a^16
            ci[p] = nc[p] ^ SGN;                    // +c_seg
        }
    }
#pragma unroll
    for (int k = 0; k < 5; k++) {
#pragma unroll
        for (int p = 0; p < 3; p++) {
            u64 cp = __shfl_up_sync(0xffffffffu, ci[p], 1u << k);
            if (lane >= (1 << k)) ci[p] = f2fma(mk[p], cp, ci[p]);
            mk[p] = f2mul(mk[p], mk[p]);
        }
    }                                               // mk = a^512
    u64 cle[3];
#pragma unroll
    for (int p = 0; p < 3; p++) {
        cle[p] = __shfl_up_sync(0xffffffffu, ci[p], 1);
        if (lane == 0) cle[p] = 0;
    }
    if (lane == 31) {
        s_cw[wid][0] = ci[0]; s_cw[wid][1] = ci[1]; s_cw[wid][2] = ci[2];
    }
    __syncthreads();

    // ---- cross-warp combine + per-thread start levels ----
    // Ls = Q*(a^(512*wid)*y0 + E) + cle, Q = a^(16*lane)
    float y0 = s_d[0];
    u64 y0p = pk(y0, y0);
    float l16 = 16.0f * lane;
    u64 Ls[3];
#pragma unroll
    for (int p = 0; p < 3; p++) {
        u64 E = 0;
        for (int w = 0; w < wid; w++) E = f2fma(mk[p], E, s_cw[w][p]);
        u64 base = y0p;
        u64 m2 = f2mul(mk[p], mk[p]);               // a^1024
        u64 m4 = f2mul(m2, m2);                     // a^2048
        if (wid & 1) base = f2mul(base, mk[p]);
        if (wid & 2) base = f2mul(base, m2);
        if (wid & 4) base = f2mul(base, m4);
        base = f2add(base, E);
        u64 Q = pk(exp2f(l16 * c_l2a[2 * p]), exp2f(l16 * c_l2a[2 * p + 1]));
        Ls[p] = f2fma(Q, base, cle[p]);
        if (tid == 0) {
            u64 Ct = 0;
#pragma unroll
            for (int w = 0; w < 8; w++) Ct = f2fma(mk[p], Ct, s_cw[w][p]);
            u64 A = f2mul(m4, m4);                  // a^4096
            float flo, fhi; upk(f2fma(A, y0p, Ct), flo, fhi);
            g_finals[b * NS + 2 * p]     = flo;
            g_finals[b * NS + 2 * p + 1] = fhi;
        }
    }
    if (tid == 255) g_finals[b * NS + 6] = yp[15];  // sigma=1: last y

    // ---- pass 2: exact packed recurrence from segment starts ----
    float prev = (tid == 0) ? y0 : *(yp - 5);       // element 16t-1
    u64 nL[3], er[3];
#pragma unroll
    for (int p = 0; p < 3; p++) { nL[p] = Ls[p] ^ SGN; er[p] = 0; }
    float e6 = 0.f, pv = prev;                      // sigma=1: indep diffs
#pragma unroll
    for (int q = 0; q < 4; q++) {
        float4 v = *(const float4*)(yp + q * 4);
        float e4[4] = {v.x, v.y, v.z, v.w};
#pragma unroll
        for (int j = 0; j < 4; j++) {
            u64 yy = pk(e4[j], e4[j]);
#pragma unroll
            for (int p = 0; p < 3; p++) {
                u64 d = f2add(yy, nL[p]);          // y - L
                er[p] = f2fma(d, d, er[p]);
                nL[p] = f2fma(nsg[p], d, nL[p]);   // L += s*d (negated)
            }
            float d6 = e4[j] - pv;
            e6 = fmaf(d6, d6, e6);
            pv = e4[j];
        }
    }
#pragma unroll
    for (int p = 0; p < 3; p++) {
#pragma unroll
        for (int off = 16; off; off >>= 1)
            er[p] = f2add(er[p], __shfl_down_sync(0xffffffffu, er[p], off));
    }
#pragma unroll
    for (int off = 16; off; off >>= 1)
        e6 += __shfl_down_sync(0xffffffffu, e6, off);
    if (lane == 0) {
        s_er[wid][0] = er[0]; s_er[wid][1] = er[1];
        s_er[wid][2] = er[2]; s_er[wid][3] = pk(e6, 0.f);
    }
    __syncthreads();
    if (tid < 4) {
        u64 acc = 0;
#pragma unroll
        for (int w = 0; w < 8; w++) acc = f2add(acc, s_er[w][tid]);
        float lo, hi; upk(acc, lo, hi);
        if (tid < 3) {
            g_errs[b * NS + 2 * tid]     = lo * (1.0f / (float)T);
            g_errs[b * NS + 2 * tid + 1] = hi * (1.0f / (float)T);
        } else {
            g_errs[b * NS + 6] = lo * (1.0f / (float)T);
        }
    }
}

// ---------------------------------------------------------------------------
// K2: batch-sequential pick as parallel prefix scans (proven version).
// ---------------------------------------------------------------------------
__global__ void pick_kernel() {
    __shared__ float s_rmin[B];
    __shared__ int   s_loc[B];
    __shared__ float bufA[B];
    __shared__ float bufB[B];
    int tid = threadIdx.x;

#pragma unroll
    for (int k = 0; k < 2; k++) {
        int b = tid + k * 1024;
        float best = INFINITY; int bi = 0;
#pragma unroll
        for (int s = 0; s < NS; s++) {
            float e = g_errs[b * NS + s];
            if (e < best) { best = e; bi = s; }    // strict < -> first argmin
        }
        s_rmin[b] = best; s_loc[b] = bi; bufA[b] = best;
    }
    __syncthreads();

    float* in = bufA; float* out = bufB;
    for (int off = 1; off < B; off <<= 1) {
#pragma unroll
        for (int k = 0; k < 2; k++) {
            int b = tid + k * 1024;
            float v = in[b];
            if (b >= off) v = fminf(v, in[b - off]);
            out[b] = v;
        }
        __syncthreads();
        float* tmp = in; in = out; out = tmp;
    }
#pragma unroll
    for (int k = 0; k < 2; k++) {
        int b = tid + k * 1024;
        float epm = (b == 0) ? INFINITY : in[b - 1];
        int imp = (s_rmin[b] < epm) ? 1 : 0;
        out[b] = imp ? (float)b : -1.0f;
    }
    __syncthreads();

    float* in2 = out; float* out2 = in;
    for (int off = 1; off < B; off <<= 1) {
#pragma unroll
        for (int k = 0; k < 2; k++) {
            int b = tid + k * 1024;
            float v = in2[b];
            if (b >= off) v = fmaxf(v, in2[b - off]);
            out2[b] = v;
        }
        __syncthreads();
        float* tmp = in2; in2 = out2; out2 = tmp;
    }

#pragma unroll
    for (int k = 0; k < 2; k++) {
        int b = tid + k * 1024;
        int src = (int)in2[b];
        g_src[b]  = src;
        g_sloc[b] = s_loc[src];
    }
}

// ---------------------------------------------------------------------------
// K3 (fused): prefetch data[b] into registers, then recompute filt of row
// src[b] via a 256-thread affine block scan (hiding the prefetch latency),
// then subtract from registers and store. pr written up front.
// ---------------------------------------------------------------------------
__global__ __launch_bounds__(256) void fused_out_kernel(
    const float* __restrict__ data, float* __restrict__ out1,
    float* __restrict__ out_pr) {
    __shared__ float s_row[SROW2_SZ];
    __shared__ float sA[256], sC[256];

    int b = blockIdx.x;
    int src  = g_src[b];
    int sloc = g_sloc[b];
    float sigma = c_lrs[sloc];
    float a = 1.0f - sigma;
    int t = threadIdx.x;

    // prefetch this row's data (coalesced) — consumed after the scan
    const float4* drow = (const float4*)(data + (size_t)b * T);
    float4 dv[4];
#pragma unroll
    for (int k = 0; k < 4; k++) dv[k] = __ldg(drow + t + k * 256);

    if (t < PRED / 4) {
        float pvv = g_finals[b * NS + sloc];
        ((float4*)(out_pr + (size_t)b * PRED))[t] = make_float4(pvv, pvv, pvv, pvv);
    }

    const float* srow = data + (size_t)src * T;
    for (int i = t; i < T; i += 256)
        s_row[SIDX2(i)] = __ldg(srow + i);
    __syncthreads();

    const int SEG = T / 256;                          // 16
    int base = t * SEG;
    float A = a;
#pragma unroll
    for (int i = 0; i < 4; i++) A *= A;               // a^16

    float c = 0.0f;
#pragma unroll
    for (int j = 0; j < SEG; j++)
        c = fmaf(a, c, sigma * s_row[SIDX2(base + j)]);

    sA[t] = A; sC[t] = c;
    __syncthreads();
    float Ai = A, ci = c;
    for (int off = 1; off < 256; off <<= 1) {
        float Ap = 0.0f, cp = 0.0f;
        if (t >= off) { Ap = sA[t - off]; cp = sC[t - off]; }
        __syncthreads();
        if (t >= off) { ci = fmaf(Ai, cp, ci); Ai *= Ap; }
        sA[t] = Ai; sC[t] = ci;
        __syncthreads();
    }
    float y0 = s_row[0];
    float L = (t == 0) ? y0 : fmaf(sA[t - 1], y0, sC[t - 1]);

    // pass 2: overwrite src row in smem with its filt values
#pragma unroll
    for (int j = 0; j < SEG; j++) {
        int idx = SIDX2(base + j);
        float y = s_row[idx];
        s_row[idx] = L;                // filt[t] = pre-update level
        float d = y - L;
        L = fmaf(sigma, d, L);
    }
    __syncthreads();

    // out1[b] = data[b] - filt (data from prefetched regs)
    float4* orow = (float4*)(out1 + (size_t)b * T);
#pragma unroll
    for (int k = 0; k < 4; k++) {
        int i = t + k * 256;
        int j = i * 4;
        float4 r;
        r.x = dv[k].x - s_row[SIDX2(j)];
        r.y = dv[k].y - s_row[SIDX2(j + 1)];
        r.z = dv[k].z - s_row[SIDX2(j + 2)];
        r.w = dv[k].w - s_row[SIDX2(j + 3)];
        orow[i] = r;
    }
}

// ---------------------------------------------------------------------------
extern "C" void kernel_launch(void* const* d_in, const int* in_sizes, int n_in,
                              void* d_out, int out_size) {
    const float* data = (const float*)d_in[0];
    float* out = (float*)d_out;
    float* out1 = out;                       // [B, T]  data - sm
    float* out_pr = out + (size_t)B * T;     // [B, 64] forecast

    scan_kernel<<<B, 256>>>(data);
    pick_kernel<<<1, 1024>>>();
    fused_out_kernel<<<B, 256>>>(data, out1, out_pr);
}